// round 9
// baseline (speedup 1.0000x reference)
#include <cuda_runtime.h>
#include <math.h>
#include <stdint.h>

// Fixed problem shapes
#define BB   4
#define SS   2048
#define GG   8
#define DD   128
#define NN   64
#define BG   (BB*GG)          // 32
#define NTOK (BB*SS*GG)       // 65536
#define SUB  32
#define NSUB (SS/SUB)         // 64

// Scratch (device globals; no allocation allowed)
__device__ float4 g_ab[BG*SS*NN];      // (a_r, a_i, bxr*dt, bxi*dt)  64 MB
__device__ float4 g_hc[BG*SS*NN];      // (hl_r, hl_i, c_r, c_i)      64 MB
__device__ float2 g_hin[BG*NSUB*NN];   // subchunk input states        1 MB

// ---------------- helpers ----------------
__device__ __forceinline__ uint32_t cvt_tf32(float f) {
    uint32_t u; asm("cvt.rna.tf32.f32 %0, %1;" : "=r"(u) : "f"(f)); return u;
}
__device__ __forceinline__ float tf32f(float f) {
    return __uint_as_float(cvt_tf32(f));
}
__device__ __forceinline__ void mma8(float* c, uint32_t a0, uint32_t a1,
                                     uint32_t a2, uint32_t a3,
                                     uint32_t b0, uint32_t b1) {
    asm("mma.sync.aligned.m16n8k8.row.col.f32.tf32.tf32.f32 "
        "{%0,%1,%2,%3}, {%4,%5,%6,%7}, {%8,%9}, {%0,%1,%2,%3};"
        : "+f"(c[0]), "+f"(c[1]), "+f"(c[2]), "+f"(c[3])
        : "r"(a0), "r"(a1), "r"(a2), "r"(a3), "r"(b0), "r"(b1));
}
__device__ __forceinline__ float clampdt(float v) {
    return fminf(fmaxf(v, 1e-4f), 2.0f);
}
// packed column position: pairs (k, k+4) adjacent for LDS.64 fragment loads
__device__ __forceinline__ int unpos(int c) {
    int slot = c & 7;
    return (c & ~7) + (slot >> 1) + ((slot & 1) << 2);
}
__device__ __forceinline__ int posf(int k) {
    return (k & ~7) + ((k & 3) << 1) + ((k & 4) >> 2);
}
// exp(z) on [-2.75, 0.05]: Taylor deg-10 about -1.375 (abs err < 1e-6)
__device__ __forceinline__ float pexp(float z) {
    const float t = z + 1.375f;
    float r = 6.96758145405495e-08f;
    r = fmaf(r, t, 6.96758145405495e-07f);
    r = fmaf(r, t, 6.27082330864946e-06f);
    r = fmaf(r, t, 5.01665864691957e-05f);
    r = fmaf(r, t, 3.51166105284370e-04f);
    r = fmaf(r, t, 2.10699663170622e-03f);
    r = fmaf(r, t, 1.05349831585311e-02f);
    r = fmaf(r, t, 4.21399326341243e-02f);
    r = fmaf(r, t, 1.26419797902373e-01f);
    r = fmaf(r, t, 2.52839595804746e-01f);
    r = fmaf(r, t, 2.52839595804746e-01f);
    return r;
}
// sin/cos Taylor, |w| <= 2 (abs err < 2e-6)
__device__ __forceinline__ void psincos(float w, float& s, float& c) {
    float w2 = w * w;
    float sr = -2.50521083854417e-08f;
    sr = fmaf(sr, w2, 2.75573192239859e-06f);
    sr = fmaf(sr, w2, -1.98412698412698e-04f);
    sr = fmaf(sr, w2, 8.33333333333333e-03f);
    sr = fmaf(sr, w2, -1.66666666666667e-01f);
    s = fmaf(sr * w2, w, w);
    float cr = 2.08767569878681e-09f;
    cr = fmaf(cr, w2, -2.75573192239859e-07f);
    cr = fmaf(cr, w2, 2.48015873015873e-05f);
    cr = fmaf(cr, w2, -1.38888888888889e-03f);
    cr = fmaf(cr, w2, 4.16666666666667e-02f);
    cr = fmaf(cr, w2, -5.0e-01f);
    c = fmaf(cr, w2, 1.0f);
}

// ---------------------------------------------------------------------------
// Kernel 1: tf32 MMA projection. Warp = 16 tokens. A-fragments double-buffered
// in registers (prefetch distance = one full 17-MMA block).
// ---------------------------------------------------------------------------
__global__ __launch_bounds__(256, 2) void k1_mma(
    const float* __restrict__ xr_g, const float* __restrict__ xi_g,
    const float* __restrict__ logA, const float* __restrict__ Aph_g,
    const float* __restrict__ Bwr,  const float* __restrict__ Bwi,
    const float* __restrict__ dtw_g, const float* __restrict__ dtb_g)
{
    extern __shared__ float sm[];
    float* BRp = sm;                 // [72][136]
    float* BIp = BRp + 72*136;       // [72][136]
    float* nlA = BIp + 72*136;       // [512]
    float* aph = nlA + 512;          // [512]

    const int tid = threadIdx.x;
    for (int idx = tid; idx < 72*136; idx += 256) {
        int r = idx / 136, c = idx - r*136;
        float vr = 0.f, vi = 0.f;
        if (c < 128 && r < 66) {
            int k = unpos(c);
            if (r < 64)      { vr = Bwr[r*128 + k];   vi = Bwi[r*128 + k]; }
            else if (r == 64){ vr = dtw_g[k];         vi = dtw_g[128 + k]; }
            else             { vr = dtw_g[256 + k];   vi = dtw_g[384 + k]; }
        }
        BRp[idx] = tf32f(vr);
        BIp[idx] = tf32f(vi);
    }
    for (int i = tid; i < 512; i += 256) {
        nlA[i] = -log1pf(expf(logA[i]));   // -softplus
        aph[i] = Aph_g[i];
    }
    __syncthreads();

    const int w = tid >> 5, l = tid & 31;
    const int q = l >> 2, j = l & 3;
    const int tau0 = (blockIdx.x*8 + w)*16;
    const int b = tau0 >> 14;
    const int s0 = (tau0 >> 3) & 2047;

    float cr[9][4], ci[8][4];
    #pragma unroll
    for (int t = 0; t < 9; ++t) { cr[t][0]=0.f; cr[t][1]=0.f; cr[t][2]=0.f; cr[t][3]=0.f; }
    #pragma unroll
    for (int t = 0; t < 8; ++t) { ci[t][0]=0.f; ci[t][1]=0.f; ci[t][2]=0.f; ci[t][3]=0.f; }

    const size_t rowA = (size_t)(tau0 + q)*128;
    const size_t rowB = (size_t)(tau0 + q + 8)*128;

    // preload ks=0 A fragments (xr)
    uint32_t ca0, ca1, ca2, ca3;
    {
        const int kk = j;
        ca0 = cvt_tf32(__ldg(xr_g + rowA + kk));
        ca1 = cvt_tf32(__ldg(xr_g + rowB + kk));
        ca2 = cvt_tf32(__ldg(xr_g + rowA + kk + 4));
        ca3 = cvt_tf32(__ldg(xr_g + rowB + kk + 4));
    }

    #pragma unroll
    for (int ks = 0; ks < 32; ++ks) {
        // ---- prefetch next A fragments ----
        uint32_t na0 = 0, na1 = 0, na2 = 0, na3 = 0;
        if (ks < 31) {
            const float* xs = ((ks + 1) < 16) ? xr_g : xi_g;
            const int kk = ((ks + 1) & 15)*8 + j;
            na0 = cvt_tf32(__ldg(xs + rowA + kk));
            na1 = cvt_tf32(__ldg(xs + rowB + kk));
            na2 = cvt_tf32(__ldg(xs + rowA + kk + 4));
            na3 = cvt_tf32(__ldg(xs + rowB + kk + 4));
        }

        const int kc = (ks & 15)*8 + 2*j;
        if (ks < 16) {
            // xr half: Bx_r += xr*Bwr ; dt += xr*dtw_lo ; Bx_i += xr*Bwi
            #pragma unroll
            for (int nt = 0; nt < 9; ++nt) {
                uint2 bb = *(const uint2*)&BRp[(nt*8 + q)*136 + kc];
                mma8(cr[nt], ca0, ca1, ca2, ca3, bb.x, bb.y);
            }
            #pragma unroll
            for (int nt = 0; nt < 8; ++nt) {
                uint2 bb = *(const uint2*)&BIp[(nt*8 + q)*136 + kc];
                mma8(ci[nt], ca0, ca1, ca2, ca3, bb.x, bb.y);
            }
        } else {
            // xi half: Bx_r -= xi*Bwi ; dt += xi*dtw_hi ; Bx_i += xi*Bwr
            #pragma unroll
            for (int nt = 0; nt < 9; ++nt) {
                uint2 bb = *(const uint2*)&BIp[(nt*8 + q)*136 + kc];
                uint32_t m = (nt < 8) ? 0x80000000u : 0u;
                mma8(cr[nt], ca0, ca1, ca2, ca3, bb.x ^ m, bb.y ^ m);
            }
            #pragma unroll
            for (int nt = 0; nt < 8; ++nt) {
                uint2 bb = *(const uint2*)&BRp[(nt*8 + q)*136 + kc];
                mma8(ci[nt], ca0, ca1, ca2, ca3, bb.x, bb.y);
            }
        }
        ca0 = na0; ca1 = na1; ca2 = na2; ca3 = na3;
    }

    // ---- epilogue: dt via shfl, A via poly, write g_ab ----
    const float db0 = dtb_g[0], db1 = dtb_g[1];
    const int src = l & ~3;   // lane with j==0 in this group
    float dmL = __shfl_sync(0xffffffffu, cr[8][0], src);
    float dpL = __shfl_sync(0xffffffffu, cr[8][1], src);
    float dmH = __shfl_sync(0xffffffffu, cr[8][2], src);
    float dpH = __shfl_sync(0xffffffffu, cr[8][3], src);
    dmL = clampdt(__expf(dmL + db0));  dpL = clampdt(__expf(dpL + db1));
    dmH = clampdt(__expf(dmH + db0));  dpH = clampdt(__expf(dpH + db1));

    // token q: (b, g=q, s=s0); token q+8: (b, g=q, s=s0+1)
    const size_t idxL = ((size_t)(b*8 + q)*2048 + s0)*64;
    const size_t idxH = idxL + 64;

    #pragma unroll
    for (int nt = 0; nt < 8; ++nt) {
        int n0 = nt*8 + 2*j;
        float nl0 = nlA[q*64 + n0], nl1 = nlA[q*64 + n0 + 1];
        float ap0 = aph[q*64 + n0], ap1 = aph[q*64 + n0 + 1];
        float am, sn, cs;
        am = pexp(dmL*nl0); psincos(dpL*ap0, sn, cs);
        g_ab[idxL + n0]     = make_float4(am*cs, am*sn, cr[nt][0]*dmL, ci[nt][0]*dmL);
        am = pexp(dmL*nl1); psincos(dpL*ap1, sn, cs);
        g_ab[idxL + n0 + 1] = make_float4(am*cs, am*sn, cr[nt][1]*dmL, ci[nt][1]*dmL);
        am = pexp(dmH*nl0); psincos(dpH*ap0, sn, cs);
        g_ab[idxH + n0]     = make_float4(am*cs, am*sn, cr[nt][2]*dmH, ci[nt][2]*dmH);
        am = pexp(dmH*nl1); psincos(dpH*ap1, sn, cs);
        g_ab[idxH + n0 + 1] = make_float4(am*cs, am*sn, cr[nt][3]*dmH, ci[nt][3]*dmH);
    }
}

// ---------------------------------------------------------------------------
// Kernel 2a: per-subchunk (32 tokens) local scan from 0; store (h_local, c).
// ---------------------------------------------------------------------------
__global__ __launch_bounds__(64) void k2a_sub(void)
{
    int blk = blockIdx.x;                 // 0..2047
    int bg = blk >> 6, sub = blk & 63;
    int n = threadIdx.x;
    size_t base = ((size_t)bg*SS + sub*SUB)*NN + n;

    float hr = 0.f, hi = 0.f, cr = 1.f, ci = 0.f;
    float4 buf[8];
    #pragma unroll
    for (int jj = 0; jj < 8; ++jj) buf[jj] = g_ab[base + (size_t)jj*NN];

    #pragma unroll
    for (int t0 = 0; t0 < SUB; t0 += 8) {
        #pragma unroll
        for (int jj = 0; jj < 8; ++jj) {
            float4 a = buf[jj];
            int tn = t0 + 8 + jj;
            if (tn < SUB) buf[jj] = g_ab[base + (size_t)tn*NN];
            float nr = fmaf(a.x, hr, fmaf(-a.y, hi, a.z));
            float ni = fmaf(a.x, hi, fmaf( a.y, hr, a.w));
            hr = nr; hi = ni;
            float qr = a.x*cr - a.y*ci;
            float qi = a.x*ci + a.y*cr;
            cr = qr; ci = qi;
            g_hc[base + (size_t)(t0 + jj)*NN] = make_float4(hr, hi, cr, ci);
        }
    }
}

// ---------------------------------------------------------------------------
// Kernel 2b: sequential subchunk combine; renorm every 8th subchunk boundary.
// ---------------------------------------------------------------------------
__global__ __launch_bounds__(64) void k2b_combine(void)
{
    int bg = blockIdx.x;
    int n = threadIdx.x;
    float hr = 0.f, hi = 0.f;

    float4 ebuf[8];
    #pragma unroll
    for (int jj = 0; jj < 8; ++jj)
        ebuf[jj] = g_hc[((size_t)bg*SS + jj*SUB + 31)*NN + n];

    for (int s0 = 0; s0 < NSUB; s0 += 8) {
        #pragma unroll
        for (int jj = 0; jj < 8; ++jj) {
            float4 e = ebuf[jj];
            int nsub = s0 + 8 + jj;
            if (nsub < NSUB)
                ebuf[jj] = g_hc[((size_t)bg*SS + nsub*SUB + 31)*NN + n];
            int sub = s0 + jj;
            g_hin[(bg*NSUB + sub)*NN + n] = make_float2(hr, hi);
            float nr = fmaf(e.z, hr, fmaf(-e.w, hi, e.x));
            float ni = fmaf(e.z, hi, fmaf( e.w, hr, e.y));
            if ((sub & 7) == 7) {
                float nm = sqrtf(nr*nr + ni*ni + 1e-8f);
                float sc = fminf(nm, 100.0f)/nm;
                nr *= sc; ni *= sc;
            }
            hr = nr; hi = ni;
        }
    }
}

// ---------------------------------------------------------------------------
// Kernel 3: correction + tf32 MMA C-projection. block = 512, CTA = 128 tokens.
// Warp task = (mpair 0..3: 32 tokens = 2 m-blocks) x (nhalf 0..1: 8 nt-tiles)
// x (half 0..1: yR/yI). Each B-fragment feeds TWO MMAs (both m-blocks);
// 12 LDS per 16 MMA. Accumulators 2x8x4 = 64 floats.
// ---------------------------------------------------------------------------
__global__ __launch_bounds__(512, 1) void k3_mma(
    const float* __restrict__ Cwr, const float* __restrict__ Cwi,
    float* __restrict__ out)
{
    extern __shared__ float sm[];
    float* P  = sm;             // [128 d][72]  Cwr, k-pair packed
    float* Q  = P + 128*72;     // [128 d][72]  Cwi
    float* hs = Q + 128*72;     // [128 tok][136]  [hr | hi], k-pair packed

    const int tid = threadIdx.x;
    for (int idx = tid; idx < 128*72; idx += 512) {
        int d = idx / 72, c = idx - d*72;
        float vp = 0.f, vq = 0.f;
        if (c < 64) {
            int k = unpos(c);
            vp = Cwr[d*64 + k];
            vq = Cwi[d*64 + k];
        }
        P[idx] = tf32f(vp);
        Q[idx] = tf32f(vq);
    }

    // ---- correction prologue: 128 tok x 64 n ----
    const int tau_base = blockIdx.x*128;
    for (int cell = tid; cell < 128*64; cell += 512) {
        int tl = cell >> 6, n = cell & 63;
        int tau = tau_base + tl;
        int b = tau >> 14, g = tau & 7, s = (tau >> 3) & 2047;
        int bg = b*8 + g;
        float4 hc = g_hc[((size_t)bg*2048 + s)*64 + n];
        float2 hin = g_hin[(bg*64 + (s >> 5))*64 + n];
        float hr = fmaf(hc.z, hin.x, fmaf(-hc.w, hin.y, hc.x));
        float hi = fmaf(hc.z, hin.y, fmaf( hc.w, hin.x, hc.y));
        if ((s & 255) == 255) {
            float nm = sqrtf(hr*hr + hi*hi + 1e-8f);
            float sc = fminf(nm, 100.0f)/nm;
            hr *= sc; hi *= sc;
        }
        int pos = posf(n);
        hs[tl*136 + pos]      = tf32f(hr);
        hs[tl*136 + 64 + pos] = tf32f(hi);
    }
    __syncthreads();

    const int w = tid >> 5, l = tid & 31;
    const int q = l >> 2, j = l & 3;
    const int mpair = w & 3;           // which 32-token block
    const int nhalf = (w >> 2) & 1;    // which 8 nt-tiles
    const int half  = w >> 3;          // 0 = yR, 1 = yI
    const int row0 = mpair*32 + q;
    const int ntb = nhalf*8;

    const float* Blo = half ? Q : P;     // k < 64
    const float* Bhi = half ? P : Q;     // k >= 64
    const uint32_t mhi = half ? 0u : 0x80000000u;   // negate Q for yR

    float y[2][8][4];
    #pragma unroll
    for (int m = 0; m < 2; ++m)
        #pragma unroll
        for (int t = 0; t < 8; ++t) { y[m][t][0]=0.f; y[m][t][1]=0.f; y[m][t][2]=0.f; y[m][t][3]=0.f; }

    // ---- hr half (k < 64) ----
    #pragma unroll
    for (int ks = 0; ks < 8; ++ks) {
        const int kc = ks*8 + 2*j;
        uint2 aA0 = *(const uint2*)&hs[row0*136 + kc];
        uint2 aA1 = *(const uint2*)&hs[(row0 + 8)*136 + kc];
        uint2 aB0 = *(const uint2*)&hs[(row0 + 16)*136 + kc];
        uint2 aB1 = *(const uint2*)&hs[(row0 + 24)*136 + kc];
        #pragma unroll
        for (int t = 0; t < 8; ++t) {
            uint2 bb = *(const uint2*)&Blo[((ntb + t)*8 + q)*72 + kc];
            mma8(y[0][t], aA0.x, aA1.x, aA0.y, aA1.y, bb.x, bb.y);
            mma8(y[1][t], aB0.x, aB1.x, aB0.y, aB1.y, bb.x, bb.y);
        }
    }
    // ---- hi half (k >= 64) ----
    #pragma unroll
    for (int ks = 0; ks < 8; ++ks) {
        const int kc = ks*8 + 2*j;
        uint2 aA0 = *(const uint2*)&hs[row0*136 + 64 + kc];
        uint2 aA1 = *(const uint2*)&hs[(row0 + 8)*136 + 64 + kc];
        uint2 aB0 = *(const uint2*)&hs[(row0 + 16)*136 + 64 + kc];
        uint2 aB1 = *(const uint2*)&hs[(row0 + 24)*136 + 64 + kc];
        #pragma unroll
        for (int t = 0; t < 8; ++t) {
            uint2 bb = *(const uint2*)&Bhi[((ntb + t)*8 + q)*72 + kc];
            mma8(y[0][t], aA0.x, aA1.x, aA0.y, aA1.y, bb.x ^ mhi, bb.y ^ mhi);
            mma8(y[1][t], aB0.x, aB1.x, aB0.y, aB1.y, bb.x ^ mhi, bb.y ^ mhi);
        }
    }

    // ---- output ----
    float* outh = out + (size_t)half * ((size_t)NTOK*128);
    #pragma unroll
    for (int t = 0; t < 8; ++t) {
        int d0 = (ntb + t)*8 + 2*j;
        size_t tA = (size_t)(tau_base + row0)*128 + d0;
        size_t tB = (size_t)(tau_base + row0 + 8)*128 + d0;
        size_t tC = (size_t)(tau_base + row0 + 16)*128 + d0;
        size_t tD = (size_t)(tau_base + row0 + 24)*128 + d0;
        *(float2*)&outh[tA] = make_float2(y[0][t][0], y[0][t][1]);
        *(float2*)&outh[tB] = make_float2(y[0][t][2], y[0][t][3]);
        *(float2*)&outh[tC] = make_float2(y[1][t][0], y[1][t][1]);
        *(float2*)&outh[tD] = make_float2(y[1][t][2], y[1][t][3]);
    }
}

// ---------------------------------------------------------------------------
extern "C" void kernel_launch(void* const* d_in, const int* in_sizes, int n_in,
                              void* d_out, int out_size)
{
    const float* x_r  = (const float*)d_in[0];
    const float* x_i  = (const float*)d_in[1];
    const float* logA = (const float*)d_in[2];
    const float* Aph  = (const float*)d_in[3];
    const float* Bwr  = (const float*)d_in[4];
    const float* Bwi  = (const float*)d_in[5];
    const float* Cwr  = (const float*)d_in[6];
    const float* Cwi  = (const float*)d_in[7];
    const float* dtw  = (const float*)d_in[8];
    const float* dtb  = (const float*)d_in[9];
    float* out = (float*)d_out;

    const int smem1 = (72*136*2 + 1024) * 4;          // 82,432 B
    const int smem3 = (128*72*2 + 128*136) * 4;       // 143,360 B
    cudaFuncSetAttribute(k1_mma, cudaFuncAttributeMaxDynamicSharedMemorySize, smem1);
    cudaFuncSetAttribute(k3_mma, cudaFuncAttributeMaxDynamicSharedMemorySize, smem3);

    k1_mma<<<512, 256, smem1>>>(x_r, x_i, logA, Aph, Bwr, Bwi, dtw, dtb);
    k2a_sub<<<BG*NSUB, 64>>>();
    k2b_combine<<<BG, 64>>>();
    k3_mma<<<512, 512, smem3>>>(Cwr, Cwi, out);
}

// round 10
// speedup vs baseline: 1.5204x; 1.5204x over previous
#include <cuda_runtime.h>
#include <math.h>
#include <stdint.h>

// Fixed problem shapes
#define BB   4
#define SS   2048
#define GG   8
#define DD   128
#define NN   64
#define BG   (BB*GG)          // 32
#define NTOK (BB*SS*GG)       // 65536
#define SUB  32
#define NSUB (SS/SUB)         // 64

// Scratch (device globals; no allocation allowed)
__device__ float4 g_ab[BG*SS*NN];      // (a_r, a_i, bxr*dt, bxi*dt)  64 MB
__device__ float4 g_hc[BG*SS*NN];      // (hl_r, hl_i, c_r, c_i)      64 MB
__device__ float2 g_hin[BG*NSUB*NN];   // subchunk input states        1 MB

// ---------------- helpers ----------------
__device__ __forceinline__ uint32_t cvt_tf32(float f) {
    uint32_t u; asm("cvt.rna.tf32.f32 %0, %1;" : "=r"(u) : "f"(f)); return u;
}
__device__ __forceinline__ float tf32f(float f) {
    return __uint_as_float(cvt_tf32(f));
}
__device__ __forceinline__ void mma8(float* c, uint32_t a0, uint32_t a1,
                                     uint32_t a2, uint32_t a3,
                                     uint32_t b0, uint32_t b1) {
    asm("mma.sync.aligned.m16n8k8.row.col.f32.tf32.tf32.f32 "
        "{%0,%1,%2,%3}, {%4,%5,%6,%7}, {%8,%9}, {%0,%1,%2,%3};"
        : "+f"(c[0]), "+f"(c[1]), "+f"(c[2]), "+f"(c[3])
        : "r"(a0), "r"(a1), "r"(a2), "r"(a3), "r"(b0), "r"(b1));
}
__device__ __forceinline__ float clampdt(float v) {
    return fminf(fmaxf(v, 1e-4f), 2.0f);
}
// packed column position: pairs (k, k+4) adjacent for LDS.64 fragment loads
__device__ __forceinline__ int unpos(int c) {
    int slot = c & 7;
    return (c & ~7) + (slot >> 1) + ((slot & 1) << 2);
}
__device__ __forceinline__ int posf(int k) {
    return (k & ~7) + ((k & 3) << 1) + ((k & 4) >> 2);
}
// exp(z) on [-2.75, 0.05]: Taylor deg-10 about -1.375 (abs err < 1e-6)
__device__ __forceinline__ float pexp(float z) {
    const float t = z + 1.375f;
    float r = 6.96758145405495e-08f;
    r = fmaf(r, t, 6.96758145405495e-07f);
    r = fmaf(r, t, 6.27082330864946e-06f);
    r = fmaf(r, t, 5.01665864691957e-05f);
    r = fmaf(r, t, 3.51166105284370e-04f);
    r = fmaf(r, t, 2.10699663170622e-03f);
    r = fmaf(r, t, 1.05349831585311e-02f);
    r = fmaf(r, t, 4.21399326341243e-02f);
    r = fmaf(r, t, 1.26419797902373e-01f);
    r = fmaf(r, t, 2.52839595804746e-01f);
    r = fmaf(r, t, 2.52839595804746e-01f);
    return r;
}
// sin/cos Taylor, |w| <= 2 (abs err < 2e-6)
__device__ __forceinline__ void psincos(float w, float& s, float& c) {
    float w2 = w * w;
    float sr = -2.50521083854417e-08f;
    sr = fmaf(sr, w2, 2.75573192239859e-06f);
    sr = fmaf(sr, w2, -1.98412698412698e-04f);
    sr = fmaf(sr, w2, 8.33333333333333e-03f);
    sr = fmaf(sr, w2, -1.66666666666667e-01f);
    s = fmaf(sr * w2, w, w);
    float cr = 2.08767569878681e-09f;
    cr = fmaf(cr, w2, -2.75573192239859e-07f);
    cr = fmaf(cr, w2, 2.48015873015873e-05f);
    cr = fmaf(cr, w2, -1.38888888888889e-03f);
    cr = fmaf(cr, w2, 4.16666666666667e-02f);
    cr = fmaf(cr, w2, -5.0e-01f);
    c = fmaf(cr, w2, 1.0f);
}

// ---------------------------------------------------------------------------
// Kernel 1: tf32 MMA projection (R8 version — unroll-2 bodies, I-cache safe).
// Warp = 16 tokens (2 s x 8 g).
// ---------------------------------------------------------------------------
__global__ __launch_bounds__(256, 2) void k1_mma(
    const float* __restrict__ xr_g, const float* __restrict__ xi_g,
    const float* __restrict__ logA, const float* __restrict__ Aph_g,
    const float* __restrict__ Bwr,  const float* __restrict__ Bwi,
    const float* __restrict__ dtw_g, const float* __restrict__ dtb_g)
{
    extern __shared__ float sm[];
    float* BRp = sm;                 // [72][136]
    float* BIp = BRp + 72*136;       // [72][136]
    float* nlA = BIp + 72*136;       // [512]
    float* aph = nlA + 512;          // [512]

    const int tid = threadIdx.x;
    for (int idx = tid; idx < 72*136; idx += 256) {
        int r = idx / 136, c = idx - r*136;
        float vr = 0.f, vi = 0.f;
        if (c < 128 && r < 66) {
            int k = unpos(c);
            if (r < 64)      { vr = Bwr[r*128 + k];   vi = Bwi[r*128 + k]; }
            else if (r == 64){ vr = dtw_g[k];         vi = dtw_g[128 + k]; }
            else             { vr = dtw_g[256 + k];   vi = dtw_g[384 + k]; }
        }
        BRp[idx] = tf32f(vr);
        BIp[idx] = tf32f(vi);
    }
    for (int i = tid; i < 512; i += 256) {
        nlA[i] = -log1pf(expf(logA[i]));   // -softplus
        aph[i] = Aph_g[i];
    }
    __syncthreads();

    const int w = tid >> 5, l = tid & 31;
    const int q = l >> 2, j = l & 3;
    const int tau0 = (blockIdx.x*8 + w)*16;
    const int b = tau0 >> 14;
    const int s0 = (tau0 >> 3) & 2047;

    float cr[9][4], ci[8][4];
    #pragma unroll
    for (int t = 0; t < 9; ++t) { cr[t][0]=0.f; cr[t][1]=0.f; cr[t][2]=0.f; cr[t][3]=0.f; }
    #pragma unroll
    for (int t = 0; t < 8; ++t) { ci[t][0]=0.f; ci[t][1]=0.f; ci[t][2]=0.f; ci[t][3]=0.f; }

    const size_t rowA = (size_t)(tau0 + q)*128;
    const size_t rowB = (size_t)(tau0 + q + 8)*128;

    // ---- xr half: Bx_r += xr*Bwr ; Bx_i += xr*Bwi ; dt += xr*dtw[:,k<128]
    #pragma unroll 2
    for (int ks = 0; ks < 16; ++ks) {
        const int kk = ks*8 + j;
        uint32_t a0 = cvt_tf32(xr_g[rowA + kk]);
        uint32_t a1 = cvt_tf32(xr_g[rowB + kk]);
        uint32_t a2 = cvt_tf32(xr_g[rowA + kk + 4]);
        uint32_t a3 = cvt_tf32(xr_g[rowB + kk + 4]);
        const int kc = ks*8 + 2*j;
        #pragma unroll
        for (int nt = 0; nt < 9; ++nt) {
            uint2 bb = *(const uint2*)&BRp[(nt*8 + q)*136 + kc];
            mma8(cr[nt], a0, a1, a2, a3, bb.x, bb.y);
        }
        #pragma unroll
        for (int nt = 0; nt < 8; ++nt) {
            uint2 bb = *(const uint2*)&BIp[(nt*8 + q)*136 + kc];
            mma8(ci[nt], a0, a1, a2, a3, bb.x, bb.y);
        }
    }
    // ---- xi half: Bx_r -= xi*Bwi ; Bx_i += xi*Bwr ; dt += xi*dtw[:,k>=128]
    #pragma unroll 2
    for (int ks = 0; ks < 16; ++ks) {
        const int kk = ks*8 + j;
        uint32_t a0 = cvt_tf32(xi_g[rowA + kk]);
        uint32_t a1 = cvt_tf32(xi_g[rowB + kk]);
        uint32_t a2 = cvt_tf32(xi_g[rowA + kk + 4]);
        uint32_t a3 = cvt_tf32(xi_g[rowB + kk + 4]);
        const int kc = ks*8 + 2*j;
        #pragma unroll
        for (int nt = 0; nt < 9; ++nt) {
            uint2 bb = *(const uint2*)&BIp[(nt*8 + q)*136 + kc];
            uint32_t m = (nt < 8) ? 0x80000000u : 0u;   // -Bwi, but +dtw
            mma8(cr[nt], a0, a1, a2, a3, bb.x ^ m, bb.y ^ m);
        }
        #pragma unroll
        for (int nt = 0; nt < 8; ++nt) {
            uint2 bb = *(const uint2*)&BRp[(nt*8 + q)*136 + kc];
            mma8(ci[nt], a0, a1, a2, a3, bb.x, bb.y);
        }
    }

    // ---- epilogue: dt via shfl, A via poly, write g_ab ----
    const float db0 = dtb_g[0], db1 = dtb_g[1];
    const int src = l & ~3;   // lane with j==0 in this group
    float dmL = __shfl_sync(0xffffffffu, cr[8][0], src);
    float dpL = __shfl_sync(0xffffffffu, cr[8][1], src);
    float dmH = __shfl_sync(0xffffffffu, cr[8][2], src);
    float dpH = __shfl_sync(0xffffffffu, cr[8][3], src);
    dmL = clampdt(__expf(dmL + db0));  dpL = clampdt(__expf(dpL + db1));
    dmH = clampdt(__expf(dmH + db0));  dpH = clampdt(__expf(dpH + db1));

    // token q: (b, g=q, s=s0); token q+8: (b, g=q, s=s0+1)
    const size_t idxL = ((size_t)(b*8 + q)*2048 + s0)*64;
    const size_t idxH = idxL + 64;

    #pragma unroll
    for (int nt = 0; nt < 8; ++nt) {
        int n0 = nt*8 + 2*j;
        float nl0 = nlA[q*64 + n0], nl1 = nlA[q*64 + n0 + 1];
        float ap0 = aph[q*64 + n0], ap1 = aph[q*64 + n0 + 1];
        float am, sn, cs;
        am = pexp(dmL*nl0); psincos(dpL*ap0, sn, cs);
        g_ab[idxL + n0]     = make_float4(am*cs, am*sn, cr[nt][0]*dmL, ci[nt][0]*dmL);
        am = pexp(dmL*nl1); psincos(dpL*ap1, sn, cs);
        g_ab[idxL + n0 + 1] = make_float4(am*cs, am*sn, cr[nt][1]*dmL, ci[nt][1]*dmL);
        am = pexp(dmH*nl0); psincos(dpH*ap0, sn, cs);
        g_ab[idxH + n0]     = make_float4(am*cs, am*sn, cr[nt][2]*dmH, ci[nt][2]*dmH);
        am = pexp(dmH*nl1); psincos(dpH*ap1, sn, cs);
        g_ab[idxH + n0 + 1] = make_float4(am*cs, am*sn, cr[nt][3]*dmH, ci[nt][3]*dmH);
    }
}

// ---------------------------------------------------------------------------
// Kernel 2a: per-subchunk (32 tokens) local scan from 0; store (h_local, c).
// ---------------------------------------------------------------------------
__global__ __launch_bounds__(64) void k2a_sub(void)
{
    int blk = blockIdx.x;                 // 0..2047
    int bg = blk >> 6, sub = blk & 63;
    int n = threadIdx.x;
    size_t base = ((size_t)bg*SS + sub*SUB)*NN + n;

    float hr = 0.f, hi = 0.f, cr = 1.f, ci = 0.f;
    float4 buf[8];
    #pragma unroll
    for (int jj = 0; jj < 8; ++jj) buf[jj] = g_ab[base + (size_t)jj*NN];

    #pragma unroll
    for (int t0 = 0; t0 < SUB; t0 += 8) {
        #pragma unroll
        for (int jj = 0; jj < 8; ++jj) {
            float4 a = buf[jj];
            int tn = t0 + 8 + jj;
            if (tn < SUB) buf[jj] = g_ab[base + (size_t)tn*NN];
            float nr = fmaf(a.x, hr, fmaf(-a.y, hi, a.z));
            float ni = fmaf(a.x, hi, fmaf( a.y, hr, a.w));
            hr = nr; hi = ni;
            float qr = a.x*cr - a.y*ci;
            float qi = a.x*ci + a.y*cr;
            cr = qr; ci = qi;
            g_hc[base + (size_t)(t0 + jj)*NN] = make_float4(hr, hi, cr, ci);
        }
    }
}

// ---------------------------------------------------------------------------
// Kernel 2b: sequential subchunk combine; renorm every 8th subchunk boundary.
// ---------------------------------------------------------------------------
__global__ __launch_bounds__(64) void k2b_combine(void)
{
    int bg = blockIdx.x;
    int n = threadIdx.x;
    float hr = 0.f, hi = 0.f;

    float4 ebuf[8];
    #pragma unroll
    for (int jj = 0; jj < 8; ++jj)
        ebuf[jj] = g_hc[((size_t)bg*SS + jj*SUB + 31)*NN + n];

    for (int s0 = 0; s0 < NSUB; s0 += 8) {
        #pragma unroll
        for (int jj = 0; jj < 8; ++jj) {
            float4 e = ebuf[jj];
            int nsub = s0 + 8 + jj;
            if (nsub < NSUB)
                ebuf[jj] = g_hc[((size_t)bg*SS + nsub*SUB + 31)*NN + n];
            int sub = s0 + jj;
            g_hin[(bg*NSUB + sub)*NN + n] = make_float2(hr, hi);
            float nr = fmaf(e.z, hr, fmaf(-e.w, hi, e.x));
            float ni = fmaf(e.z, hi, fmaf( e.w, hr, e.y));
            if ((sub & 7) == 7) {
                float nm = sqrtf(nr*nr + ni*ni + 1e-8f);
                float sc = fminf(nm, 100.0f)/nm;
                nr *= sc; ni *= sc;
            }
            hr = nr; hi = ni;
        }
    }
}

// ---------------------------------------------------------------------------
// Kernel 3: correction + tf32 MMA C-projection. CTA = 64 tokens, block = 512,
// grid = 1024, smem 108.5 KB -> 2 CTAs/SM (32 warps). Warp task =
// (mrow 0..3: 16 tokens) x (nhalf 0..1: 8 nt-tiles) x (half 0..1: yR/yI).
// Accumulators 8x4 = 32 floats -> fits 64-reg budget of launch_bounds(512,2).
// ---------------------------------------------------------------------------
__global__ __launch_bounds__(512, 2) void k3_mma(
    const float* __restrict__ Cwr, const float* __restrict__ Cwi,
    float* __restrict__ out)
{
    extern __shared__ float sm[];
    float* P  = sm;             // [128 d][72]  Cwr, k-pair packed
    float* Q  = P + 128*72;     // [128 d][72]  Cwi
    float* hs = Q + 128*72;     // [64 tok][136]  [hr | hi], k-pair packed

    const int tid = threadIdx.x;
    for (int idx = tid; idx < 128*72; idx += 512) {
        int d = idx / 72, c = idx - d*72;
        float vp = 0.f, vq = 0.f;
        if (c < 64) {
            int k = unpos(c);
            vp = Cwr[d*64 + k];
            vq = Cwi[d*64 + k];
        }
        P[idx] = tf32f(vp);
        Q[idx] = tf32f(vq);
    }

    // ---- correction prologue: 64 tok x 64 n ----
    const int tau_base = blockIdx.x*64;
    #pragma unroll
    for (int ii = 0; ii < 8; ++ii) {
        int cell = ii*512 + tid;
        int tl = cell >> 6, n = cell & 63;
        int tau = tau_base + tl;
        int b = tau >> 14, g = tau & 7, s = (tau >> 3) & 2047;
        int bg = b*8 + g;
        float4 hc = g_hc[((size_t)bg*2048 + s)*64 + n];
        float2 hin = g_hin[(bg*64 + (s >> 5))*64 + n];
        float hr = fmaf(hc.z, hin.x, fmaf(-hc.w, hin.y, hc.x));
        float hi = fmaf(hc.z, hin.y, fmaf( hc.w, hin.x, hc.y));
        if ((s & 255) == 255) {
            float nm = sqrtf(hr*hr + hi*hi + 1e-8f);
            float sc = fminf(nm, 100.0f)/nm;
            hr *= sc; hi *= sc;
        }
        int pos = posf(n);
        hs[tl*136 + pos]      = tf32f(hr);
        hs[tl*136 + 64 + pos] = tf32f(hi);
    }
    __syncthreads();

    const int w = tid >> 5, l = tid & 31;
    const int q = l >> 2, j = l & 3;
    const int mrow  = w & 3;           // which 16-token block
    const int nhalf = (w >> 2) & 1;    // which 8 nt-tiles
    const int half  = w >> 3;          // 0 = yR, 1 = yI
    const int row0 = mrow*16 + q;
    const int ntb = nhalf*8;

    const float* Blo = half ? Q : P;     // k < 64
    const float* Bhi = half ? P : Q;     // k >= 64
    const uint32_t mhi = half ? 0u : 0x80000000u;   // negate Q for yR

    float y[8][4];
    #pragma unroll
    for (int t = 0; t < 8; ++t) { y[t][0]=0.f; y[t][1]=0.f; y[t][2]=0.f; y[t][3]=0.f; }

    // ---- hr half (k < 64) ----
    #pragma unroll
    for (int ks = 0; ks < 8; ++ks) {
        const int kc = ks*8 + 2*j;
        uint2 aa0 = *(const uint2*)&hs[row0*136 + kc];
        uint2 aa1 = *(const uint2*)&hs[(row0 + 8)*136 + kc];
        #pragma unroll
        for (int t = 0; t < 8; ++t) {
            uint2 bb = *(const uint2*)&Blo[((ntb + t)*8 + q)*72 + kc];
            mma8(y[t], aa0.x, aa1.x, aa0.y, aa1.y, bb.x, bb.y);
        }
    }
    // ---- hi half (k >= 64) ----
    #pragma unroll
    for (int ks = 0; ks < 8; ++ks) {
        const int kc = ks*8 + 2*j;
        uint2 aa0 = *(const uint2*)&hs[row0*136 + 64 + kc];
        uint2 aa1 = *(const uint2*)&hs[(row0 + 8)*136 + 64 + kc];
        #pragma unroll
        for (int t = 0; t < 8; ++t) {
            uint2 bb = *(const uint2*)&Bhi[((ntb + t)*8 + q)*72 + kc];
            mma8(y[t], aa0.x, aa1.x, aa0.y, aa1.y, bb.x ^ mhi, bb.y ^ mhi);
        }
    }

    // ---- output ----
    float* outh = out + (size_t)half * ((size_t)NTOK*128);
    #pragma unroll
    for (int t = 0; t < 8; ++t) {
        int d0 = (ntb + t)*8 + 2*j;
        size_t tA = (size_t)(tau_base + row0)*128 + d0;
        size_t tB = (size_t)(tau_base + row0 + 8)*128 + d0;
        *(float2*)&outh[tA] = make_float2(y[t][0], y[t][1]);
        *(float2*)&outh[tB] = make_float2(y[t][2], y[t][3]);
    }
}

// ---------------------------------------------------------------------------
extern "C" void kernel_launch(void* const* d_in, const int* in_sizes, int n_in,
                              void* d_out, int out_size)
{
    const float* x_r  = (const float*)d_in[0];
    const float* x_i  = (const float*)d_in[1];
    const float* logA = (const float*)d_in[2];
    const float* Aph  = (const float*)d_in[3];
    const float* Bwr  = (const float*)d_in[4];
    const float* Bwi  = (const float*)d_in[5];
    const float* Cwr  = (const float*)d_in[6];
    const float* Cwi  = (const float*)d_in[7];
    const float* dtw  = (const float*)d_in[8];
    const float* dtb  = (const float*)d_in[9];
    float* out = (float*)d_out;

    const int smem1 = (72*136*2 + 1024) * 4;          // 82,432 B
    const int smem3 = (128*72*2 + 64*136) * 4;        // 108,544 B
    cudaFuncSetAttribute(k1_mma, cudaFuncAttributeMaxDynamicSharedMemorySize, smem1);
    cudaFuncSetAttribute(k3_mma, cudaFuncAttributeMaxDynamicSharedMemorySize, smem3);

    k1_mma<<<512, 256, smem1>>>(x_r, x_i, logA, Aph, Bwr, Bwi, dtw, dtb);
    k2a_sub<<<BG*NSUB, 64>>>();
    k2b_combine<<<BG, 64>>>();
    k3_mma<<<1024, 512, smem3>>>(Cwr, Cwi, out);
}